// round 9
// baseline (speedup 1.0000x reference)
#include <cuda_runtime.h>
#include <cuda_fp16.h>

#define N_NODES 100000
#define N_EDGES 1600000
#define N_PAD   100032                       // padded node rows for tile overrun
#define NBLK    ((N_NODES + 255) / 256)      // 391 scan blocks
typedef unsigned long long u64;

// ---------------- device scratch (no allocations allowed) ----------------
__device__ float  g_q[N_PAD * 64];     // fp32 Q  [n][h*8+e]
__device__ __half g_kv[N_PAD * 128];   // fp16 KV [n][h*16 + (k:0-7 | v:8-15)] -> 32B/(node,head)
__device__ float  g_x1[N_PAD * 64];    // after attention + residual + LN1
__device__ int    g_ecol[N_EDGES];     // CSR column list
__device__ int    g_cnt[N_NODES];
__device__ int    g_start[N_NODES];    // immutable CSR row starts (for attn)
__device__ int    g_startM[N_NODES];   // mutable copy consumed by scatter
__device__ u64    g_pack[NBLK + 1];    // [0..NBLK): lookback state; [NBLK]: scan-done counter
__device__ int    g_is64;

// ---------------- packed fp32x2 helpers (sm_100+) ----------------
__device__ __forceinline__ u64 fma2(u64 a, u64 b, u64 c) {
    u64 d; asm("fma.rn.f32x2 %0,%1,%2,%3;" : "=l"(d) : "l"(a), "l"(b), "l"(c)); return d;
}
__device__ __forceinline__ u64 pack2(float x, float y) {
    u64 d; asm("mov.b64 %0,{%1,%2};" : "=l"(d) : "f"(x), "f"(y)); return d;
}
__device__ __forceinline__ float2 unpack2(u64 v) {
    float2 r; asm("mov.b64 {%0,%1},%2;" : "=f"(r.x), "=f"(r.y) : "l"(v)); return r;
}

// ---------------- hist + per-block dtype detection ----------------
// If data is int32, an int64 view of slot j has hi-word = row[2j+1] (random in
// [0,1e5), almost surely nonzero) -> bounds check fails. All-32-pass when data
// is truly int32 has probability ~1e-160.
__global__ void hist_detect_kernel(const void* ei) {
    __shared__ int s_is64;
    int tid = threadIdx.x;
    if (tid < 32) {
        const long long* p = (const long long*)ei;
        long long v = p[tid];
        int ok = (v >= 0 && v < N_NODES);
        unsigned m = __ballot_sync(0xffffffffu, ok);
        if (tid == 0) {
            s_is64 = (m == 0xffffffffu);
            if (blockIdx.x == 0) g_is64 = s_is64;
        }
    }
    __syncthreads();
    int is64 = s_is64;
    int i = blockIdx.x * 256 + tid;
    if (i < N_EDGES) {
        int r = is64 ? (int)((const long long*)ei)[i] : ((const int*)ei)[i];
        atomicAdd(&g_cnt[r], 1);
    }
}

// ---------------- fused scan (decoupled lookback) + scatter ----------------
// Blocks [0,NBLK) compute the exclusive scan of g_cnt and publish g_start /
// g_startM, then bump the done counter. ALL 6250 blocks then spin (tid 0 only)
// until the counter reaches NBLK and scatter their 256 edges. Scan blocks are
// wave-1 resident (grid 6250, ~32 CTAs/SM -> wave1 >> 391), so no deadlock.
__global__ void scan_scatter_kernel(const void* ei) {
    __shared__ int s[256];
    __shared__ int s_off;
    int bid = blockIdx.x, tid = threadIdx.x;
    if (bid < NBLK) {
        int i = bid * 256 + tid;
        int v = (i < N_NODES) ? g_cnt[i] : 0;
        s[tid] = v;
        __syncthreads();
        for (int o = 1; o < 256; o <<= 1) {       // Hillis-Steele inclusive
            int t = (tid >= o) ? s[tid - o] : 0;
            __syncthreads();
            s[tid] += t;
            __syncthreads();
        }
        int total = s[255];
        if (tid == 0) {
            u64 st = (bid == 0) ? 2ULL : 1ULL;
            atomicExch(&g_pack[bid], (st << 32) | (unsigned)total);
            s_off = 0;
        }
        __syncthreads();
        if (bid > 0 && tid < 32) {                // warp-parallel lookback
            int off = 0, j = bid - 1;
            for (;;) {
                int idx = j - tid;
                u64 p = 0; int st = 0;
                if (idx >= 0) {
                    do {
                        p = *(volatile u64*)&g_pack[idx];
                        st = (int)(p >> 32);
                    } while (st == 0);
                }
                unsigned inc_mask = __ballot_sync(0xffffffffu, idx >= 0 && st == 2);
                int val;
                if (inc_mask) {
                    int lead = __ffs(inc_mask) - 1;
                    val = (tid <= lead) ? (int)(unsigned)p : 0;
#pragma unroll
                    for (int o = 16; o; o >>= 1) val += __shfl_xor_sync(0xffffffffu, val, o);
                    off += val;
                    break;
                } else {
                    val = (idx >= 0) ? (int)(unsigned)p : 0;
#pragma unroll
                    for (int o = 16; o; o >>= 1) val += __shfl_xor_sync(0xffffffffu, val, o);
                    off += val;
                    j -= 32;
                    if (j < 0) break;
                }
            }
            if (tid == 0) {
                atomicExch(&g_pack[bid], (2ULL << 32) | (unsigned)(off + total));
                s_off = off;
            }
        }
        __syncthreads();
        if (i < N_NODES) {
            int st = s_off + s[tid] - v;          // exclusive prefix
            g_start[i] = st;
            g_startM[i] = st;
        }
        __threadfence();
        __syncthreads();
        if (tid == 0) atomicAdd(&g_pack[NBLK], 1ULL);
    }
    // ---- all blocks: wait for full scan, then scatter ----
    if (tid == 0) {
        while (atomicOr(&g_pack[NBLK], 0ULL) < (u64)NBLK) __nanosleep(64);
    }
    __syncthreads();
    int i = bid * 256 + tid;                      // 6250*256 == N_EDGES exactly
    int r, c;
    if (g_is64) {
        const long long* p = (const long long*)ei;
        r = (int)p[i]; c = (int)p[N_EDGES + i];
    } else {
        const int* p = (const int*)ei;
        r = p[i]; c = p[N_EDGES + i];
    }
    int pos = atomicAdd(&g_startM[r], 1);
    g_ecol[pos] = c;
}

// ---------------- qkv GEMM: x[100k,64] @ W[64,192] + b ----------------
// 64 nodes/CTA, blockDim 192. GEMM column c: head=c/24, r=c%24 -> q(0-7) fp32,
// k/v(8-23) fp16 at head*16 + (r-8).  (reference reshape(n,H,3*Dh) + split(axis=2))
__global__ __launch_bounds__(192, 3) void qkv_kernel(const float* __restrict__ x,
                                                     const float* __restrict__ w,
                                                     const float* __restrict__ bias) {
    extern __shared__ float sm[];
    float* ws = sm;            // 64*192
    float* xs = sm + 12288;    // [64 i][66 m-slots]
    int tid = threadIdx.x;
    for (int i = tid; i < 3072; i += 192) ((float4*)ws)[i] = ((const float4*)w)[i];
    int n0 = blockIdx.x * 64;
    for (int idx = tid; idx < 4096; idx += 192) {
        int m = idx >> 6, i = idx & 63;
        int r = n0 + m;
        xs[i * 66 + m] = (r < N_NODES) ? x[r * 64 + i] : 0.f;
    }
    __syncthreads();
    int cg = tid % 48, mg = tid / 48;
    u64 acc[8][4];
#pragma unroll
    for (int k = 0; k < 4; k++) {
        float bv = bias[cg + 48 * k];
        u64 bp = pack2(bv, bv);
#pragma unroll
        for (int mp = 0; mp < 8; mp++) acc[mp][k] = bp;
    }
#pragma unroll 4
    for (int i = 0; i < 64; i++) {
        u64 xp[8];
#pragma unroll
        for (int mp = 0; mp < 8; mp++) xp[mp] = *(const u64*)&xs[i * 66 + (mg * 8 + mp) * 2];
#pragma unroll
        for (int k = 0; k < 4; k++) {
            float wv = ws[i * 192 + cg + 48 * k];
            u64 wp = pack2(wv, wv);
#pragma unroll
            for (int mp = 0; mp < 8; mp++) acc[mp][k] = fma2(xp[mp], wp, acc[mp][k]);
        }
    }
#pragma unroll
    for (int mp = 0; mp < 8; mp++) {
        int m = n0 + (mg * 8 + mp) * 2;
#pragma unroll
        for (int k = 0; k < 4; k++) {
            int c = cg + 48 * k;
            int head = c / 24, r = c % 24;     // per-head interleave: q|k|v
            float2 v = unpack2(acc[mp][k]);
            if (r < 8) {
                int off = head * 8 + r;
                g_q[m * 64 + off] = v.x;
                g_q[(m + 1) * 64 + off] = v.y;
            } else {
                int off = head * 16 + (r - 8); // k: 0-7, v: 8-15 within head
                g_kv[m * 128 + off] = __float2half_rn(v.x);
                g_kv[(m + 1) * 128 + off] = __float2half_rn(v.y);
            }
        }
    }
}

// ---------------- fused attention gather + normalize + residual + LN1 ----------------
// Warp per node, lane = (group g 0-3) x (head h 0-7). fp16 K/V, 32B/(edge,head).
// Software pipeline: ecol prefetched 2 iters ahead, K/V 1 iter ahead.
__global__ __launch_bounds__(256) void attn_kernel(const float* __restrict__ x,
                                                   const float* __restrict__ lg,
                                                   const float* __restrict__ lb) {
    __shared__ float sg[64], sb[64];
    int tid = threadIdx.x;
    if (tid < 64) sg[tid] = lg[tid];
    else if (tid < 128) sb[tid - 64] = lb[tid - 64];
    __syncthreads();
    int wid = tid >> 5, lane = tid & 31;
    int n = blockIdx.x * 8 + wid;
    int h = lane & 7, g = lane >> 3;
    const float4* qb = (const float4*)(g_q + n * 64 + h * 8);
    float4 q0 = qb[0], q1 = qb[1];
    const float4* xb = (const float4*)(x + n * 64 + h * 8);   // hoisted residual load
    float4 x0 = xb[0], x1v = xb[1];
    float den = 0.f;
    float a[8];
#pragma unroll
    for (int j = 0; j < 8; j++) a[j] = 0.f;
    int s = g_start[n], e = s + g_cnt[n];

    int i = s + g;
    bool v0 = i < e, v1 = i + 4 < e;
    int c1 = 0;
    uint4 kr = make_uint4(0, 0, 0, 0), vr = make_uint4(0, 0, 0, 0);
    if (v0) {
        int c0 = g_ecol[i];
        const uint4* p = (const uint4*)(g_kv + c0 * 128 + h * 16);
        kr = p[0]; vr = p[1];
    }
    if (v1) c1 = g_ecol[i + 4];
    while (v0) {
        uint4 krn = make_uint4(0, 0, 0, 0), vrn = make_uint4(0, 0, 0, 0);
        if (v1) {
            const uint4* p = (const uint4*)(g_kv + c1 * 128 + h * 16);
            krn = p[0]; vrn = p[1];
        }
        bool v2 = i + 8 < e;
        int c2 = 0;
        if (v2) c2 = g_ecol[i + 8];
        // compute on current kr/vr
        float2 k0 = __half22float2(*(__half2*)&kr.x);
        float2 k1 = __half22float2(*(__half2*)&kr.y);
        float2 k2 = __half22float2(*(__half2*)&kr.z);
        float2 k3 = __half22float2(*(__half2*)&kr.w);
        float d = q0.x * k0.x + q0.y * k0.y + q0.z * k1.x + q0.w * k1.y
                + q1.x * k2.x + q1.y * k2.y + q1.z * k3.x + q1.w * k3.y;
        float ev = __expf(d * 0.125f);
        den += ev;
        float2 v0f = __half22float2(*(__half2*)&vr.x);
        float2 v1f = __half22float2(*(__half2*)&vr.y);
        float2 v2f = __half22float2(*(__half2*)&vr.z);
        float2 v3f = __half22float2(*(__half2*)&vr.w);
        a[0] += ev * v0f.x; a[1] += ev * v0f.y; a[2] += ev * v1f.x; a[3] += ev * v1f.y;
        a[4] += ev * v2f.x; a[5] += ev * v2f.y; a[6] += ev * v3f.x; a[7] += ev * v3f.y;
        // rotate pipeline
        kr = krn; vr = vrn;
        c1 = c2; v0 = v1; v1 = v2;
        i += 4;
    }
    // reduce across the 4 edge-groups
#pragma unroll
    for (int o = 8; o <= 16; o <<= 1) {
        den += __shfl_xor_sync(0xffffffffu, den, o);
#pragma unroll
        for (int j = 0; j < 8; j++) a[j] += __shfl_xor_sync(0xffffffffu, a[j], o);
    }
    float inv = (den > 0.f) ? 1.f / den : 0.f;
    float z[8];
    z[0] = x0.x + a[0] * inv;  z[1] = x0.y + a[1] * inv;
    z[2] = x0.z + a[2] * inv;  z[3] = x0.w + a[3] * inv;
    z[4] = x1v.x + a[4] * inv; z[5] = x1v.y + a[5] * inv;
    z[6] = x1v.z + a[6] * inv; z[7] = x1v.w + a[7] * inv;
    float sum = 0.f, sq = 0.f;
#pragma unroll
    for (int j = 0; j < 8; j++) { sum += z[j]; sq += z[j] * z[j]; }
#pragma unroll
    for (int o = 1; o < 8; o <<= 1) {
        sum += __shfl_xor_sync(0xffffffffu, sum, o);
        sq  += __shfl_xor_sync(0xffffffffu, sq, o);
    }
    float mean = sum * (1.f / 64.f);
    float rstd = rsqrtf(sq * (1.f / 64.f) - mean * mean + 1e-5f);
    if (g == 0) {
        float4 o0, o1;
        o0.x = (z[0] - mean) * rstd * sg[h * 8 + 0] + sb[h * 8 + 0];
        o0.y = (z[1] - mean) * rstd * sg[h * 8 + 1] + sb[h * 8 + 1];
        o0.z = (z[2] - mean) * rstd * sg[h * 8 + 2] + sb[h * 8 + 2];
        o0.w = (z[3] - mean) * rstd * sg[h * 8 + 3] + sb[h * 8 + 3];
        o1.x = (z[4] - mean) * rstd * sg[h * 8 + 4] + sb[h * 8 + 4];
        o1.y = (z[5] - mean) * rstd * sg[h * 8 + 5] + sb[h * 8 + 5];
        o1.z = (z[6] - mean) * rstd * sg[h * 8 + 6] + sb[h * 8 + 6];
        o1.w = (z[7] - mean) * rstd * sg[h * 8 + 7] + sb[h * 8 + 7];
        float4* ob = (float4*)(g_x1 + n * 64 + h * 8);
        ob[0] = o0; ob[1] = o1;
    }
}

// ---------------- fused FFN: out = LN2(x1 + relu(x1@W1+b1)@W2+b2) ----------------
__global__ __launch_bounds__(256, 1) void ffn_kernel(const float* __restrict__ w1,
                                                     const float* __restrict__ b1,
                                                     const float* __restrict__ w2,
                                                     const float* __restrict__ b2,
                                                     const float* __restrict__ lg,
                                                     const float* __restrict__ lb,
                                                     float* __restrict__ out) {
    extern __shared__ float sm[];
    float* w1s = sm;             // 16384
    float* w2s = sm + 16384;     // 16384
    float* xs  = sm + 32768;     // [64 i][66 m] (reused as zs[64 m][66 c])
    float* hs  = sm + 36992;     // [256 j][66 m]
    int tid = threadIdx.x;
    for (int i = tid; i < 4096; i += 256) {
        ((float4*)w1s)[i] = ((const float4*)w1)[i];
        ((float4*)w2s)[i] = ((const float4*)w2)[i];
    }
    int cg = tid & 63, mg = tid >> 6;
    int cg2 = tid & 31, mg2 = tid >> 5;
    int wid = tid >> 5, lane = tid & 31;
    u64 b1p[4], b2p[2];
#pragma unroll
    for (int k = 0; k < 4; k++) { float bv = b1[cg + 64 * k]; b1p[k] = pack2(bv, bv); }
#pragma unroll
    for (int k = 0; k < 2; k++) { float bv = b2[cg2 + 32 * k]; b2p[k] = pack2(bv, bv); }
    float lgA = lg[lane], lgB = lg[lane + 32], lbA = lb[lane], lbB = lb[lane + 32];
    __syncthreads();

    for (int tile = blockIdx.x; tile < 1563; tile += 148) {
        int n0 = tile * 64;
        for (int idx = tid; idx < 4096; idx += 256) {
            int m = idx >> 6, i = idx & 63;
            xs[i * 66 + m] = g_x1[(n0 + m) * 64 + i];
        }
        __syncthreads();
        u64 acc[8][4];
#pragma unroll
        for (int mp = 0; mp < 8; mp++)
#pragma unroll
            for (int k = 0; k < 4; k++) acc[mp][k] = b1p[k];
#pragma unroll 4
        for (int i = 0; i < 64; i++) {
            u64 xp[8];
#pragma unroll
            for (int mp = 0; mp < 8; mp++) xp[mp] = *(const u64*)&xs[i * 66 + (mg * 8 + mp) * 2];
#pragma unroll
            for (int k = 0; k < 4; k++) {
                float wv = w1s[i * 256 + cg + 64 * k];
                u64 wp = pack2(wv, wv);
#pragma unroll
                for (int mp = 0; mp < 8; mp++) acc[mp][k] = fma2(xp[mp], wp, acc[mp][k]);
            }
        }
#pragma unroll
        for (int mp = 0; mp < 8; mp++)
#pragma unroll
            for (int k = 0; k < 4; k++) {
                float2 v = unpack2(acc[mp][k]);
                v.x = fmaxf(v.x, 0.f); v.y = fmaxf(v.y, 0.f);
                *(float2*)&hs[(cg + 64 * k) * 66 + (mg * 8 + mp) * 2] = v;
            }
        __syncthreads();
        u64 a2[4][2];
#pragma unroll
        for (int mp = 0; mp < 4; mp++)
#pragma unroll
            for (int k = 0; k < 2; k++) a2[mp][k] = b2p[k];
#pragma unroll 4
        for (int j = 0; j < 256; j++) {
            u64 hp[4];
#pragma unroll
            for (int mp = 0; mp < 4; mp++) hp[mp] = *(const u64*)&hs[j * 66 + (mg2 * 4 + mp) * 2];
#pragma unroll
            for (int k = 0; k < 2; k++) {
                float wv = w2s[j * 64 + cg2 + 32 * k];
                u64 wp = pack2(wv, wv);
#pragma unroll
                for (int mp = 0; mp < 4; mp++) a2[mp][k] = fma2(hp[mp], wp, a2[mp][k]);
            }
        }
        float zr[4][2][2];
#pragma unroll
        for (int mp = 0; mp < 4; mp++)
#pragma unroll
            for (int k = 0; k < 2; k++) {
                int c = cg2 + 32 * k, m0 = (mg2 * 4 + mp) * 2;
                float2 v = unpack2(a2[mp][k]);
                zr[mp][k][0] = v.x + xs[c * 66 + m0];
                zr[mp][k][1] = v.y + xs[c * 66 + m0 + 1];
            }
        __syncthreads();
        float* zs = xs;
#pragma unroll
        for (int mp = 0; mp < 4; mp++)
#pragma unroll
            for (int k = 0; k < 2; k++) {
                int c = cg2 + 32 * k, m0 = (mg2 * 4 + mp) * 2;
                zs[m0 * 66 + c] = zr[mp][k][0];
                zs[(m0 + 1) * 66 + c] = zr[mp][k][1];
            }
        __syncthreads();
#pragma unroll
        for (int mm = 0; mm < 8; mm++) {
            int m = wid * 8 + mm;
            float z1 = zs[m * 66 + lane], z2 = zs[m * 66 + 32 + lane];
            float s = z1 + z2, q = z1 * z1 + z2 * z2;
#pragma unroll
            for (int o = 16; o; o >>= 1) {
                s += __shfl_xor_sync(0xffffffffu, s, o);
                q += __shfl_xor_sync(0xffffffffu, q, o);
            }
            float mean = s * (1.f / 64.f);
            float rstd = rsqrtf(q * (1.f / 64.f) - mean * mean + 1e-5f);
            int n = n0 + m;
            if (n < N_NODES) {
                out[n * 64 + lane]      = (z1 - mean) * rstd * lgA + lbA;
                out[n * 64 + lane + 32] = (z2 - mean) * rstd * lgB + lbB;
            }
        }
        __syncthreads();
    }
}

// ---------------- launch: CSR (2 kernels + memsets) forked under qkv ----------------
extern "C" void kernel_launch(void* const* d_in, const int* in_sizes, int n_in,
                              void* d_out, int out_size) {
    const float* x      = (const float*)d_in[0];
    const void*  ei     = d_in[1];
    const float* attn_w = (const float*)d_in[2];
    const float* attn_b = (const float*)d_in[3];
    const float* w1     = (const float*)d_in[4];
    const float* b1     = (const float*)d_in[5];
    const float* w2     = (const float*)d_in[6];
    const float* b2     = (const float*)d_in[7];
    const float* l1g    = (const float*)d_in[8];
    const float* l1b    = (const float*)d_in[9];
    const float* l2g    = (const float*)d_in[10];
    const float* l2b    = (const float*)d_in[11];
    float* out = (float*)d_out;

    static cudaStream_t s2 = nullptr;
    static cudaEvent_t evA = nullptr, evB = nullptr;
    static void *p_cnt = nullptr, *p_pack = nullptr;
    if (s2 == nullptr) {
        cudaStreamCreateWithFlags(&s2, cudaStreamNonBlocking);
        cudaEventCreateWithFlags(&evA, cudaEventDisableTiming);
        cudaEventCreateWithFlags(&evB, cudaEventDisableTiming);
        cudaGetSymbolAddress(&p_cnt, g_cnt);
        cudaGetSymbolAddress(&p_pack, g_pack);
    }

    cudaFuncSetAttribute(qkv_kernel, cudaFuncAttributeMaxDynamicSharedMemorySize, 66048);
    cudaFuncSetAttribute(ffn_kernel, cudaFuncAttributeMaxDynamicSharedMemorySize, 215552);

    // fork: CSR build chain on s2 (independent of qkv GEMM)
    cudaEventRecord(evA, 0);
    cudaStreamWaitEvent(s2, evA, 0);
    cudaMemsetAsync(p_cnt, 0, N_NODES * sizeof(int), s2);
    cudaMemsetAsync(p_pack, 0, (NBLK + 1) * sizeof(u64), s2);
    hist_detect_kernel<<<(N_EDGES + 255) / 256, 256, 0, s2>>>(ei);
    scan_scatter_kernel<<<N_EDGES / 256, 256, 0, s2>>>(ei);
    cudaEventRecord(evB, s2);

    // main stream: qkv GEMM overlaps with CSR build
    qkv_kernel<<<(N_NODES + 63) / 64, 192, 66048>>>(x, attn_w, attn_b);

    // join, then attention + FFN
    cudaStreamWaitEvent(0, evB, 0);
    attn_kernel<<<(N_NODES + 7) / 8, 256>>>(x, l1g, l1b);
    ffn_kernel<<<148, 256, 215552>>>(w1, b1, w2, b2, l2g, l2b, out);
}

// round 12
// speedup vs baseline: 1.0060x; 1.0060x over previous
#include <cuda_runtime.h>
#include <cuda_fp16.h>

#define N_NODES 100000
#define N_EDGES 1600000
#define N_PAD   100032                       // padded node rows for tile overrun
#define NBLK    ((N_NODES + 255) / 256)      // 391 scan blocks
typedef unsigned long long u64;

// ---------------- device scratch (no allocations allowed) ----------------
__device__ float  g_q[N_PAD * 64];     // fp32 Q  [n][h*8+e]
__device__ __half g_kv[N_PAD * 128];   // fp16 KV [n][h*16 + (k:0-7 | v:8-15)] -> 32B/(node,head)
__device__ float  g_x1[N_PAD * 64];    // after attention + residual + LN1
__device__ int    g_ecol[N_EDGES];     // CSR column list
__device__ int    g_start[N_NODES];    // immutable CSR row starts (for attn)
__device__ int    g_startM[N_NODES];   // mutable; after scatter holds start+deg (row end)
__device__ int    g_is64;

// one contiguous zeroed-every-call region -> single cudaMemsetAsync
struct CsrScratch {
    int cnt[N_NODES];
    u64 pack[NBLK + 1];   // [0..NBLK): lookback state (hi32: 1=partial 2=inclusive, lo32=value); [NBLK]: done counter
};
__device__ CsrScratch g_csr;

// ---------------- packed fp32x2 helpers (sm_100+) ----------------
__device__ __forceinline__ u64 fma2(u64 a, u64 b, u64 c) {
    u64 d; asm("fma.rn.f32x2 %0,%1,%2,%3;" : "=l"(d) : "l"(a), "l"(b), "l"(c)); return d;
}
__device__ __forceinline__ u64 pack2(float x, float y) {
    u64 d; asm("mov.b64 %0,{%1,%2};" : "=l"(d) : "f"(x), "f"(y)); return d;
}
__device__ __forceinline__ float2 unpack2(u64 v) {
    float2 r; asm("mov.b64 {%0,%1},%2;" : "=f"(r.x), "=f"(r.y) : "l"(v)); return r;
}

// ---------------- hist + per-block dtype detection ----------------
// int64 view of int32 data has hi-word = row[2j+1] (random in [0,1e5), a.s.
// nonzero) -> bounds check fails. All-32-pass on int32 data: prob ~1e-160.
__global__ void hist_detect_kernel(const void* ei) {
    __shared__ int s_is64;
    int tid = threadIdx.x;
    if (tid < 32) {
        const long long* p = (const long long*)ei;
        long long v = p[tid];
        int ok = (v >= 0 && v < N_NODES);
        unsigned m = __ballot_sync(0xffffffffu, ok);
        if (tid == 0) {
            s_is64 = (m == 0xffffffffu);
            if (blockIdx.x == 0) g_is64 = s_is64;
        }
    }
    __syncthreads();
    int is64 = s_is64;
    int i = blockIdx.x * 256 + tid;
    if (i < N_EDGES) {
        int r = is64 ? (int)((const long long*)ei)[i] : ((const int*)ei)[i];
        atomicAdd(&g_csr.cnt[r], 1);
    }
}

// ---------------- fused scan (decoupled lookback) + scatter ----------------
// Blocks [0,NBLK) scan g_csr.cnt, publish g_start/g_startM, bump done counter.
// All 6250 blocks then spin (tid 0) until counter==NBLK and scatter 256 edges.
// Scan blocks are wave-1 resident (grid 6250 >> 391 first-wave slots).
__global__ void scan_scatter_kernel(const void* ei) {
    __shared__ int s[256];
    __shared__ int s_off;
    int bid = blockIdx.x, tid = threadIdx.x;
    if (bid < NBLK) {
        int i = bid * 256 + tid;
        int v = (i < N_NODES) ? g_csr.cnt[i] : 0;
        s[tid] = v;
        __syncthreads();
        for (int o = 1; o < 256; o <<= 1) {       // Hillis-Steele inclusive
            int t = (tid >= o) ? s[tid - o] : 0;
            __syncthreads();
            s[tid] += t;
            __syncthreads();
        }
        int total = s[255];
        if (tid == 0) {
            u64 st = (bid == 0) ? 2ULL : 1ULL;
            atomicExch(&g_csr.pack[bid], (st << 32) | (unsigned)total);
            s_off = 0;
        }
        __syncthreads();
        if (bid > 0 && tid < 32) {                // warp-parallel lookback
            int off = 0, j = bid - 1;
            for (;;) {
                int idx = j - tid;
                u64 p = 0; int st = 0;
                if (idx >= 0) {
                    do {
                        p = *(volatile u64*)&g_csr.pack[idx];
                        st = (int)(p >> 32);
                    } while (st == 0);
                }
                unsigned inc_mask = __ballot_sync(0xffffffffu, idx >= 0 && st == 2);
                int val;
                if (inc_mask) {
                    int lead = __ffs(inc_mask) - 1;
                    val = (tid <= lead) ? (int)(unsigned)p : 0;
#pragma unroll
                    for (int o = 16; o; o >>= 1) val += __shfl_xor_sync(0xffffffffu, val, o);
                    off += val;
                    break;
                } else {
                    val = (idx >= 0) ? (int)(unsigned)p : 0;
#pragma unroll
                    for (int o = 16; o; o >>= 1) val += __shfl_xor_sync(0xffffffffu, val, o);
                    off += val;
                    j -= 32;
                    if (j < 0) break;
                }
            }
            if (tid == 0) {
                atomicExch(&g_csr.pack[bid], (2ULL << 32) | (unsigned)(off + total));
                s_off = off;
            }
        }
        __syncthreads();
        if (i < N_NODES) {
            int st = s_off + s[tid] - v;          // exclusive prefix
            g_start[i] = st;
            g_startM[i] = st;
        }
        __threadfence();
        __syncthreads();
        if (tid == 0) atomicAdd(&g_csr.pack[NBLK], 1ULL);
    }
    // ---- all blocks: wait for full scan, then scatter ----
    if (tid == 0) {
        while (atomicOr(&g_csr.pack[NBLK], 0ULL) < (u64)NBLK) __nanosleep(64);
    }
    __syncthreads();
    int i = bid * 256 + tid;                      // 6250*256 == N_EDGES exactly
    int r, c;
    if (g_is64) {
        const long long* p = (const long long*)ei;
        r = (int)p[i]; c = (int)p[N_EDGES + i];
    } else {
        const int* p = (const int*)ei;
        r = p[i]; c = p[N_EDGES + i];
    }
    int pos = atomicAdd(&g_startM[r], 1);
    g_ecol[pos] = c;
}

// ---------------- qkv GEMM: x[100k,64] @ W[64,192] + b ----------------
// 64 nodes/CTA, blockDim 192. GEMM column c: head=c/24, r=c%24 -> q(0-7) fp32,
// k/v(8-23) fp16 at head*16 + (r-8).  (reference reshape(n,H,3*Dh) + split(axis=2))
__global__ __launch_bounds__(192, 3) void qkv_kernel(const float* __restrict__ x,
                                                     const float* __restrict__ w,
                                                     const float* __restrict__ bias) {
    extern __shared__ float sm[];
    float* ws = sm;            // 64*192
    float* xs = sm + 12288;    // [64 i][66 m-slots]
    int tid = threadIdx.x;
    for (int i = tid; i < 3072; i += 192) ((float4*)ws)[i] = ((const float4*)w)[i];
    int n0 = blockIdx.x * 64;
    for (int idx = tid; idx < 4096; idx += 192) {
        int m = idx >> 6, i = idx & 63;
        int r = n0 + m;
        xs[i * 66 + m] = (r < N_NODES) ? x[r * 64 + i] : 0.f;
    }
    __syncthreads();
    int cg = tid % 48, mg = tid / 48;
    u64 acc[8][4];
#pragma unroll
    for (int k = 0; k < 4; k++) {
        float bv = bias[cg + 48 * k];
        u64 bp = pack2(bv, bv);
#pragma unroll
        for (int mp = 0; mp < 8; mp++) acc[mp][k] = bp;
    }
#pragma unroll 4
    for (int i = 0; i < 64; i++) {
        u64 xp[8];
#pragma unroll
        for (int mp = 0; mp < 8; mp++) xp[mp] = *(const u64*)&xs[i * 66 + (mg * 8 + mp) * 2];
#pragma unroll
        for (int k = 0; k < 4; k++) {
            float wv = ws[i * 192 + cg + 48 * k];
            u64 wp = pack2(wv, wv);
#pragma unroll
            for (int mp = 0; mp < 8; mp++) acc[mp][k] = fma2(xp[mp], wp, acc[mp][k]);
        }
    }
#pragma unroll
    for (int mp = 0; mp < 8; mp++) {
        int m = n0 + (mg * 8 + mp) * 2;
#pragma unroll
        for (int k = 0; k < 4; k++) {
            int c = cg + 48 * k;
            int head = c / 24, r = c % 24;     // per-head interleave: q|k|v
            float2 v = unpack2(acc[mp][k]);
            if (r < 8) {
                int off = head * 8 + r;
                g_q[m * 64 + off] = v.x;
                g_q[(m + 1) * 64 + off] = v.y;
            } else {
                int off = head * 16 + (r - 8); // k: 0-7, v: 8-15 within head
                g_kv[m * 128 + off] = __float2half_rn(v.x);
                g_kv[(m + 1) * 128 + off] = __float2half_rn(v.y);
            }
        }
    }
}

// ---------------- fused attention gather + normalize + residual + LN1 ----------------
// Warp per node, lane = (group g 0-3) x (head h 0-7). fp16 K/V, 32B/(edge,head).
// q.k dot in HFMA2 (q pre-converted to half2), v-accumulation in fp32.
__global__ __launch_bounds__(256) void attn_kernel(const float* __restrict__ x,
                                                   const float* __restrict__ lg,
                                                   const float* __restrict__ lb) {
    __shared__ float sg[64], sb[64];
    int tid = threadIdx.x;
    if (tid < 64) sg[tid] = lg[tid];
    else if (tid < 128) sb[tid - 64] = lb[tid - 64];
    __syncthreads();
    int wid = tid >> 5, lane = tid & 31;
    int n = blockIdx.x * 8 + wid;
    int h = lane & 7, g = lane >> 3;
    const float4* qb = (const float4*)(g_q + n * 64 + h * 8);
    float4 q0 = qb[0], q1 = qb[1];
    __half2 qh0 = __floats2half2_rn(q0.x, q0.y);
    __half2 qh1 = __floats2half2_rn(q0.z, q0.w);
    __half2 qh2 = __floats2half2_rn(q1.x, q1.y);
    __half2 qh3 = __floats2half2_rn(q1.z, q1.w);
    const float4* xb = (const float4*)(x + n * 64 + h * 8);   // hoisted residual load
    float4 x0 = xb[0], x1v = xb[1];
    float den = 0.f;
    float a[8];
#pragma unroll
    for (int j = 0; j < 8; j++) a[j] = 0.f;
    int s = g_start[n];
    int e = g_startM[n];                           // = start[n] + deg[n] post-scatter
    int i = s + g;
    int c = (i < e) ? g_ecol[i] : 0;
    while (i < e) {
        int c_cur = c;
        i += 4;
        if (i < e) c = g_ecol[i];                  // prefetch next column index
        const uint4* p = (const uint4*)(g_kv + c_cur * 128 + h * 16);
        uint4 kr = p[0], vr = p[1];
        __half2 d2 = __hmul2(qh0, *(__half2*)&kr.x);
        d2 = __hfma2(qh1, *(__half2*)&kr.y, d2);
        d2 = __hfma2(qh2, *(__half2*)&kr.z, d2);
        d2 = __hfma2(qh3, *(__half2*)&kr.w, d2);
        float d = __low2float(d2) + __high2float(d2);
        float ev = __expf(d * 0.125f);
        den += ev;
        float2 v0 = __half22float2(*(__half2*)&vr.x);
        float2 v1 = __half22float2(*(__half2*)&vr.y);
        float2 v2 = __half22float2(*(__half2*)&vr.z);
        float2 v3 = __half22float2(*(__half2*)&vr.w);
        a[0] += ev * v0.x; a[1] += ev * v0.y; a[2] += ev * v1.x; a[3] += ev * v1.y;
        a[4] += ev * v2.x; a[5] += ev * v2.y; a[6] += ev * v3.x; a[7] += ev * v3.y;
    }
    // reduce across the 4 edge-groups
#pragma unroll
    for (int o = 8; o <= 16; o <<= 1) {
        den += __shfl_xor_sync(0xffffffffu, den, o);
#pragma unroll
        for (int j = 0; j < 8; j++) a[j] += __shfl_xor_sync(0xffffffffu, a[j], o);
    }
    float inv = (den > 0.f) ? 1.f / den : 0.f;
    float z[8];
    z[0] = x0.x + a[0] * inv;  z[1] = x0.y + a[1] * inv;
    z[2] = x0.z + a[2] * inv;  z[3] = x0.w + a[3] * inv;
    z[4] = x1v.x + a[4] * inv; z[5] = x1v.y + a[5] * inv;
    z[6] = x1v.z + a[6] * inv; z[7] = x1v.w + a[7] * inv;
    float sum = 0.f, sq = 0.f;
#pragma unroll
    for (int j = 0; j < 8; j++) { sum += z[j]; sq += z[j] * z[j]; }
#pragma unroll
    for (int o = 1; o < 8; o <<= 1) {
        sum += __shfl_xor_sync(0xffffffffu, sum, o);
        sq  += __shfl_xor_sync(0xffffffffu, sq, o);
    }
    float mean = sum * (1.f / 64.f);
    float rstd = rsqrtf(sq * (1.f / 64.f) - mean * mean + 1e-5f);
    if (g == 0) {
        float4 o0, o1;
        o0.x = (z[0] - mean) * rstd * sg[h * 8 + 0] + sb[h * 8 + 0];
        o0.y = (z[1] - mean) * rstd * sg[h * 8 + 1] + sb[h * 8 + 1];
        o0.z = (z[2] - mean) * rstd * sg[h * 8 + 2] + sb[h * 8 + 2];
        o0.w = (z[3] - mean) * rstd * sg[h * 8 + 3] + sb[h * 8 + 3];
        o1.x = (z[4] - mean) * rstd * sg[h * 8 + 4] + sb[h * 8 + 4];
        o1.y = (z[5] - mean) * rstd * sg[h * 8 + 5] + sb[h * 8 + 5];
        o1.z = (z[6] - mean) * rstd * sg[h * 8 + 6] + sb[h * 8 + 6];
        o1.w = (z[7] - mean) * rstd * sg[h * 8 + 7] + sb[h * 8 + 7];
        float4* ob = (float4*)(g_x1 + n * 64 + h * 8);
        ob[0] = o0; ob[1] = o1;
    }
}

// ---------------- fused FFN: out = LN2(x1 + relu(x1@W1+b1)@W2+b2) ----------------
__global__ __launch_bounds__(256, 1) void ffn_kernel(const float* __restrict__ w1,
                                                     const float* __restrict__ b1,
                                                     const float* __restrict__ w2,
                                                     const float* __restrict__ b2,
                                                     const float* __restrict__ lg,
                                                     const float* __restrict__ lb,
                                                     float* __restrict__ out) {
    extern __shared__ float sm[];
    float* w1s = sm;             // 16384
    float* w2s = sm + 16384;     // 16384
    float* xs  = sm + 32768;     // [64 i][66 m] (reused as zs[64 m][66 c])
    float* hs  = sm + 36992;     // [256 j][66 m]
    int tid = threadIdx.x;
    for (int i = tid; i < 4096; i += 256) {
        ((float4*)w1s)[i] = ((const float4*)w1)[i];
        ((float4*)w2s)[i] = ((const float4*)w2)[i];
    }
    int cg = tid & 63, mg = tid >> 6;
    int cg2 = tid & 31, mg2 = tid >> 5;
    int wid = tid >> 5, lane = tid & 31;
    u64 b1p[4], b2p[2];
#pragma unroll
    for (int k = 0; k < 4; k++) { float bv = b1[cg + 64 * k]; b1p[k] = pack2(bv, bv); }
#pragma unroll
    for (int k = 0; k < 2; k++) { float bv = b2[cg2 + 32 * k]; b2p[k] = pack2(bv, bv); }
    float lgA = lg[lane], lgB = lg[lane + 32], lbA = lb[lane], lbB = lb[lane + 32];
    __syncthreads();

    for (int tile = blockIdx.x; tile < 1563; tile += 148) {
        int n0 = tile * 64;
        for (int idx = tid; idx < 4096; idx += 256) {
            int m = idx >> 6, i = idx & 63;
            xs[i * 66 + m] = g_x1[(n0 + m) * 64 + i];
        }
        __syncthreads();
        u64 acc[8][4];
#pragma unroll
        for (int mp = 0; mp < 8; mp++)
#pragma unroll
            for (int k = 0; k < 4; k++) acc[mp][k] = b1p[k];
#pragma unroll 4
        for (int i = 0; i < 64; i++) {
            u64 xp[8];
#pragma unroll
            for (int mp = 0; mp < 8; mp++) xp[mp] = *(const u64*)&xs[i * 66 + (mg * 8 + mp) * 2];
#pragma unroll
            for (int k = 0; k < 4; k++) {
                float wv = w1s[i * 256 + cg + 64 * k];
                u64 wp = pack2(wv, wv);
#pragma unroll
                for (int mp = 0; mp < 8; mp++) acc[mp][k] = fma2(xp[mp], wp, acc[mp][k]);
            }
        }
#pragma unroll
        for (int mp = 0; mp < 8; mp++)
#pragma unroll
            for (int k = 0; k < 4; k++) {
                float2 v = unpack2(acc[mp][k]);
                v.x = fmaxf(v.x, 0.f); v.y = fmaxf(v.y, 0.f);
                *(float2*)&hs[(cg + 64 * k) * 66 + (mg * 8 + mp) * 2] = v;
            }
        __syncthreads();
        u64 a2[4][2];
#pragma unroll
        for (int mp = 0; mp < 4; mp++)
#pragma unroll
            for (int k = 0; k < 2; k++) a2[mp][k] = b2p[k];
#pragma unroll 4
        for (int j = 0; j < 256; j++) {
            u64 hp[4];
#pragma unroll
            for (int mp = 0; mp < 4; mp++) hp[mp] = *(const u64*)&hs[j * 66 + (mg2 * 4 + mp) * 2];
#pragma unroll
            for (int k = 0; k < 2; k++) {
                float wv = w2s[j * 64 + cg2 + 32 * k];
                u64 wp = pack2(wv, wv);
#pragma unroll
                for (int mp = 0; mp < 4; mp++) a2[mp][k] = fma2(hp[mp], wp, a2[mp][k]);
            }
        }
        float zr[4][2][2];
#pragma unroll
        for (int mp = 0; mp < 4; mp++)
#pragma unroll
            for (int k = 0; k < 2; k++) {
                int c = cg2 + 32 * k, m0 = (mg2 * 4 + mp) * 2;
                float2 v = unpack2(a2[mp][k]);
                zr[mp][k][0] = v.x + xs[c * 66 + m0];
                zr[mp][k][1] = v.y + xs[c * 66 + m0 + 1];
            }
        __syncthreads();
        float* zs = xs;
#pragma unroll
        for (int mp = 0; mp < 4; mp++)
#pragma unroll
            for (int k = 0; k < 2; k++) {
                int c = cg2 + 32 * k, m0 = (mg2 * 4 + mp) * 2;
                zs[m0 * 66 + c] = zr[mp][k][0];
                zs[(m0 + 1) * 66 + c] = zr[mp][k][1];
            }
        __syncthreads();
#pragma unroll
        for (int mm = 0; mm < 8; mm++) {
            int m = wid * 8 + mm;
            float z1 = zs[m * 66 + lane], z2 = zs[m * 66 + 32 + lane];
            float s = z1 + z2, q = z1 * z1 + z2 * z2;
#pragma unroll
            for (int o = 16; o; o >>= 1) {
                s += __shfl_xor_sync(0xffffffffu, s, o);
                q += __shfl_xor_sync(0xffffffffu, q, o);
            }
            float mean = s * (1.f / 64.f);
            float rstd = rsqrtf(q * (1.f / 64.f) - mean * mean + 1e-5f);
            int n = n0 + m;
            if (n < N_NODES) {
                out[n * 64 + lane]      = (z1 - mean) * rstd * lgA + lbA;
                out[n * 64 + lane + 32] = (z2 - mean) * rstd * lgB + lbB;
            }
        }
        __syncthreads();
    }
}

// ---------------- launch: CSR (1 memset + 2 kernels) forked under qkv ----------------
extern "C" void kernel_launch(void* const* d_in, const int* in_sizes, int n_in,
                              void* d_out, int out_size) {
    const float* x      = (const float*)d_in[0];
    const void*  ei     = d_in[1];
    const float* attn_w = (const float*)d_in[2];
    const float* attn_b = (const float*)d_in[3];
    const float* w1     = (const float*)d_in[4];
    const float* b1     = (const float*)d_in[5];
    const float* w2     = (const float*)d_in[6];
    const float* b2     = (const float*)d_in[7];
    const float* l1g    = (const float*)d_in[8];
    const float* l1b    = (const float*)d_in[9];
    const float* l2g    = (const float*)d_in[10];
    const float* l2b    = (const float*)d_in[11];
    float* out = (float*)d_out;

    static cudaStream_t s2 = nullptr;
    static cudaEvent_t evA = nullptr, evB = nullptr;
    static void* p_csr = nullptr;
    if (s2 == nullptr) {
        cudaStreamCreateWithFlags(&s2, cudaStreamNonBlocking);
        cudaEventCreateWithFlags(&evA, cudaEventDisableTiming);
        cudaEventCreateWithFlags(&evB, cudaEventDisableTiming);
        cudaGetSymbolAddress(&p_csr, g_csr);
    }

    cudaFuncSetAttribute(qkv_kernel, cudaFuncAttributeMaxDynamicSharedMemorySize, 66048);
    cudaFuncSetAttribute(ffn_kernel, cudaFuncAttributeMaxDynamicSharedMemorySize, 215552);

    // fork: CSR build chain on s2 (independent of qkv GEMM)
    cudaEventRecord(evA, 0);
    cudaStreamWaitEvent(s2, evA, 0);
    cudaMemsetAsync(p_csr, 0, sizeof(CsrScratch), s2);
    hist_detect_kernel<<<(N_EDGES + 255) / 256, 256, 0, s2>>>(ei);
    scan_scatter_kernel<<<N_EDGES / 256, 256, 0, s2>>>(ei);
    cudaEventRecord(evB, s2);

    // main stream: qkv GEMM overlaps with CSR build
    qkv_kernel<<<(N_NODES + 63) / 64, 192, 66048>>>(x, attn_w, attn_b);

    // join, then attention + FFN
    cudaStreamWaitEvent(0, evB, 0);
    attn_kernel<<<(N_NODES + 7) / 8, 256>>>(x, l1g, l1b);
    ffn_kernel<<<148, 256, 215552>>>(w1, b1, w2, b2, l2g, l2b, out);
}

// round 14
// speedup vs baseline: 1.0081x; 1.0021x over previous
#include <cuda_runtime.h>
#include <cuda_fp16.h>

#define N_NODES 100000
#define N_EDGES 1600000
#define N_PAD   100032                       // qkv padding (64-node tiles)
#define N_PAD2  100096                       // ffn padding (128-node tiles, 782 tiles)
#define FT      782
#define NBLK    ((N_NODES + 255) / 256)      // 391 scan blocks
typedef unsigned long long u64;

// ---------------- device scratch (no allocations allowed) ----------------
__device__ float  g_q[N_PAD * 64];     // fp32 Q  [n][h*8+e]
__device__ __half g_kv[N_PAD * 128];   // fp16 KV [n][h*16 + (k:0-7 | v:8-15)] -> 32B/(node,head)
__device__ float  g_x1[N_PAD2 * 64];   // after attention + residual + LN1
__device__ int    g_ecol[N_EDGES];     // CSR column list
__device__ int    g_start[N_NODES];    // immutable CSR row starts (for attn)
__device__ int    g_startM[N_NODES];   // mutable; after scatter holds start+deg (row end)
__device__ int    g_is64;

// one contiguous zeroed-every-call region -> single cudaMemsetAsync
struct CsrScratch {
    int cnt[N_NODES];
    u64 pack[NBLK];   // lookback state (hi32: 1=partial 2=inclusive, lo32=value)
};
__device__ CsrScratch g_csr;

// ---------------- packed fp32x2 helpers (sm_100+) ----------------
__device__ __forceinline__ u64 fma2(u64 a, u64 b, u64 c) {
    u64 d; asm("fma.rn.f32x2 %0,%1,%2,%3;" : "=l"(d) : "l"(a), "l"(b), "l"(c)); return d;
}
__device__ __forceinline__ u64 pack2(float x, float y) {
    u64 d; asm("mov.b64 %0,{%1,%2};" : "=l"(d) : "f"(x), "f"(y)); return d;
}
__device__ __forceinline__ float2 unpack2(u64 v) {
    float2 r; asm("mov.b64 {%0,%1},%2;" : "=f"(r.x), "=f"(r.y) : "l"(v)); return r;
}

// ---------------- hist + per-block dtype detection ----------------
__global__ void hist_detect_kernel(const void* ei) {
    __shared__ int s_is64;
    int tid = threadIdx.x;
    if (tid < 32) {
        const long long* p = (const long long*)ei;
        long long v = p[tid];
        int ok = (v >= 0 && v < N_NODES);
        unsigned m = __ballot_sync(0xffffffffu, ok);
        if (tid == 0) {
            s_is64 = (m == 0xffffffffu);
            if (blockIdx.x == 0) g_is64 = s_is64;
        }
    }
    __syncthreads();
    int is64 = s_is64;
    int i = blockIdx.x * 256 + tid;
    if (i < N_EDGES) {
        int r = is64 ? (int)((const long long*)ei)[i] : ((const int*)ei)[i];
        atomicAdd(&g_csr.cnt[r], 1);
    }
}

// ---------------- single-pass decoupled-lookback exclusive scan ----------------
__global__ void scan_kernel() {
    __shared__ int s[256];
    __shared__ int s_off;
    int bid = blockIdx.x, tid = threadIdx.x;
    int i = bid * 256 + tid;
    int v = (i < N_NODES) ? g_csr.cnt[i] : 0;
    s[tid] = v;
    __syncthreads();
    for (int o = 1; o < 256; o <<= 1) {           // Hillis-Steele inclusive
        int t = (tid >= o) ? s[tid - o] : 0;
        __syncthreads();
        s[tid] += t;
        __syncthreads();
    }
    int total = s[255];
    if (tid == 0) {
        u64 st = (bid == 0) ? 2ULL : 1ULL;
        atomicExch(&g_csr.pack[bid], (st << 32) | (unsigned)total);
        s_off = 0;
    }
    __syncthreads();
    if (bid > 0 && tid < 32) {                    // warp-parallel lookback
        int off = 0, j = bid - 1;
        for (;;) {
            int idx = j - tid;
            u64 p = 0; int st = 0;
            if (idx >= 0) {
                do {
                    p = *(volatile u64*)&g_csr.pack[idx];
                    st = (int)(p >> 32);
                } while (st == 0);
            }
            unsigned inc_mask = __ballot_sync(0xffffffffu, idx >= 0 && st == 2);
            int val;
            if (inc_mask) {
                int lead = __ffs(inc_mask) - 1;
                val = (tid <= lead) ? (int)(unsigned)p : 0;
#pragma unroll
                for (int o = 16; o; o >>= 1) val += __shfl_xor_sync(0xffffffffu, val, o);
                off += val;
                break;
            } else {
                val = (idx >= 0) ? (int)(unsigned)p : 0;
#pragma unroll
                for (int o = 16; o; o >>= 1) val += __shfl_xor_sync(0xffffffffu, val, o);
                off += val;
                j -= 32;
                if (j < 0) break;
            }
        }
        if (tid == 0) {
            atomicExch(&g_csr.pack[bid], (2ULL << 32) | (unsigned)(off + total));
            s_off = off;
        }
    }
    __syncthreads();
    if (i < N_NODES) {
        int st = s_off + s[tid] - v;              // exclusive prefix
        g_start[i] = st;
        g_startM[i] = st;
    }
}

__global__ void scatter_kernel(const void* ei) {
    int i = blockIdx.x * 256 + threadIdx.x;       // 6250*256 == N_EDGES exactly
    int r, c;
    if (g_is64) {
        const long long* p = (const long long*)ei;
        r = (int)p[i]; c = (int)p[N_EDGES + i];
    } else {
        const int* p = (const int*)ei;
        r = p[i]; c = p[N_EDGES + i];
    }
    int pos = atomicAdd(&g_startM[r], 1);
    g_ecol[pos] = c;
}

// ---------------- qkv GEMM: x[100k,64] @ W[64,192] + b ----------------
// 64 nodes/CTA, blockDim 192. GEMM column c: head=c/24, r=c%24 -> q(0-7) fp32,
// k/v(8-23) fp16 at head*16 + (r-8).  (reference reshape(n,H,3*Dh) + split(axis=2))
__global__ __launch_bounds__(192, 3) void qkv_kernel(const float* __restrict__ x,
                                                     const float* __restrict__ w,
                                                     const float* __restrict__ bias) {
    extern __shared__ float sm[];
    float* ws = sm;            // 64*192
    float* xs = sm + 12288;    // [64 i][66 m-slots]
    int tid = threadIdx.x;
    for (int i = tid; i < 3072; i += 192) ((float4*)ws)[i] = ((const float4*)w)[i];
    int n0 = blockIdx.x * 64;
    for (int idx = tid; idx < 4096; idx += 192) {
        int m = idx >> 6, i = idx & 63;
        int r = n0 + m;
        xs[i * 66 + m] = (r < N_NODES) ? x[r * 64 + i] : 0.f;
    }
    __syncthreads();
    int cg = tid % 48, mg = tid / 48;
    u64 acc[8][4];
#pragma unroll
    for (int k = 0; k < 4; k++) {
        float bv = bias[cg + 48 * k];
        u64 bp = pack2(bv, bv);
#pragma unroll
        for (int mp = 0; mp < 8; mp++) acc[mp][k] = bp;
    }
#pragma unroll 4
    for (int i = 0; i < 64; i++) {
        u64 xp[8];
#pragma unroll
        for (int mp = 0; mp < 8; mp++) xp[mp] = *(const u64*)&xs[i * 66 + (mg * 8 + mp) * 2];
#pragma unroll
        for (int k = 0; k < 4; k++) {
            float wv = ws[i * 192 + cg + 48 * k];
            u64 wp = pack2(wv, wv);
#pragma unroll
            for (int mp = 0; mp < 8; mp++) acc[mp][k] = fma2(xp[mp], wp, acc[mp][k]);
        }
    }
#pragma unroll
    for (int mp = 0; mp < 8; mp++) {
        int m = n0 + (mg * 8 + mp) * 2;
#pragma unroll
        for (int k = 0; k < 4; k++) {
            int c = cg + 48 * k;
            int head = c / 24, r = c % 24;     // per-head interleave: q|k|v
            float2 v = unpack2(acc[mp][k]);
            if (r < 8) {
                int off = head * 8 + r;
                g_q[m * 64 + off] = v.x;
                g_q[(m + 1) * 64 + off] = v.y;
            } else {
                int off = head * 16 + (r - 8); // k: 0-7, v: 8-15 within head
                g_kv[m * 128 + off] = __float2half_rn(v.x);
                g_kv[(m + 1) * 128 + off] = __float2half_rn(v.y);
            }
        }
    }
}

// ---------------- fused attention gather + normalize + residual + LN1 ----------------
// Warp per node, lane = (group g 0-3) x (head h 0-7). fp16 K/V, 32B/(edge,head).
// q.k dot in HFMA2 (q pre-converted to half2), v-accumulation in fp32.
__global__ __launch_bounds__(256) void attn_kernel(const float* __restrict__ x,
                                                   const float* __restrict__ lg,
                                                   const float* __restrict__ lb) {
    __shared__ float sg[64], sb[64];
    int tid = threadIdx.x;
    if (tid < 64) sg[tid] = lg[tid];
    else if (tid < 128) sb[tid - 64] = lb[tid - 64];
    __syncthreads();
    int wid = tid >> 5, lane = tid & 31;
    int n = blockIdx.x * 8 + wid;
    int h = lane & 7, g = lane >> 3;
    const float4* qb = (const float4*)(g_q + n * 64 + h * 8);
    float4 q0 = qb[0], q1 = qb[1];
    __half2 qh0 = __floats2half2_rn(q0.x, q0.y);
    __half2 qh1 = __floats2half2_rn(q0.z, q0.w);
    __half2 qh2 = __floats2half2_rn(q1.x, q1.y);
    __half2 qh3 = __floats2half2_rn(q1.z, q1.w);
    const float4* xb = (const float4*)(x + n * 64 + h * 8);   // hoisted residual load
    float4 x0 = xb[0], x1v = xb[1];
    float den = 0.f;
    float a[8];
#pragma unroll
    for (int j = 0; j < 8; j++) a[j] = 0.f;
    int s = g_start[n];
    int e = g_startM[n];                           // = start[n] + deg[n] post-scatter
    int i = s + g;
    int c = (i < e) ? g_ecol[i] : 0;
    while (i < e) {
        int c_cur = c;
        i += 4;
        if (i < e) c = g_ecol[i];                  // prefetch next column index
        const uint4* p = (const uint4*)(g_kv + c_cur * 128 + h * 16);
        uint4 kr = p[0], vr = p[1];
        __half2 d2 = __hmul2(qh0, *(__half2*)&kr.x);
        d2 = __hfma2(qh1, *(__half2*)&kr.y, d2);
        d2 = __hfma2(qh2, *(__half2*)&kr.z, d2);
        d2 = __hfma2(qh3, *(__half2*)&kr.w, d2);
        float d = __low2float(d2) + __high2float(d2);
        float ev = __expf(d * 0.125f);
        den += ev;
        float2 v0 = __half22float2(*(__half2*)&vr.x);
        float2 v1 = __half22float2(*(__half2*)&vr.y);
        float2 v2 = __half22float2(*(__half2*)&vr.z);
        float2 v3 = __half22float2(*(__half2*)&vr.w);
        a[0] += ev * v0.x; a[1] += ev * v0.y; a[2] += ev * v1.x; a[3] += ev * v1.y;
        a[4] += ev * v2.x; a[5] += ev * v2.y; a[6] += ev * v3.x; a[7] += ev * v3.y;
    }
    // reduce across the 4 edge-groups
#pragma unroll
    for (int o = 8; o <= 16; o <<= 1) {
        den += __shfl_xor_sync(0xffffffffu, den, o);
#pragma unroll
        for (int j = 0; j < 8; j++) a[j] += __shfl_xor_sync(0xffffffffu, a[j], o);
    }
    float inv = (den > 0.f) ? 1.f / den : 0.f;
    float z[8];
    z[0] = x0.x + a[0] * inv;  z[1] = x0.y + a[1] * inv;
    z[2] = x0.z + a[2] * inv;  z[3] = x0.w + a[3] * inv;
    z[4] = x1v.x + a[4] * inv; z[5] = x1v.y + a[5] * inv;
    z[6] = x1v.z + a[6] * inv; z[7] = x1v.w + a[7] * inv;
    float sum = 0.f, sq = 0.f;
#pragma unroll
    for (int j = 0; j < 8; j++) { sum += z[j]; sq += z[j] * z[j]; }
#pragma unroll
    for (int o = 1; o < 8; o <<= 1) {
        sum += __shfl_xor_sync(0xffffffffu, sum, o);
        sq  += __shfl_xor_sync(0xffffffffu, sq, o);
    }
    float mean = sum * (1.f / 64.f);
    float rstd = rsqrtf(sq * (1.f / 64.f) - mean * mean + 1e-5f);
    if (g == 0) {
        float4 o0, o1;
        o0.x = (z[0] - mean) * rstd * sg[h * 8 + 0] + sb[h * 8 + 0];
        o0.y = (z[1] - mean) * rstd * sg[h * 8 + 1] + sb[h * 8 + 1];
        o0.z = (z[2] - mean) * rstd * sg[h * 8 + 2] + sb[h * 8 + 2];
        o0.w = (z[3] - mean) * rstd * sg[h * 8 + 3] + sb[h * 8 + 3];
        o1.x = (z[4] - mean) * rstd * sg[h * 8 + 4] + sb[h * 8 + 4];
        o1.y = (z[5] - mean) * rstd * sg[h * 8 + 5] + sb[h * 8 + 5];
        o1.z = (z[6] - mean) * rstd * sg[h * 8 + 6] + sb[h * 8 + 6];
        o1.w = (z[7] - mean) * rstd * sg[h * 8 + 7] + sb[h * 8 + 7];
        float4* ob = (float4*)(g_x1 + n * 64 + h * 8);
        ob[0] = o0; ob[1] = o1;
    }
}

// ---------------- fused FFN v2: 128-node tiles, 512 threads, fp16 hidden ----------------
// smem: w1(64KB) + w2(64KB) fp32, xs [64][130] fp32 (reused as zs[128][65]),
// hs [256][130] fp16. Total 230912 B (< 232448 max).
__global__ __launch_bounds__(512, 1) void ffn_kernel(const float* __restrict__ w1,
                                                     const float* __restrict__ b1,
                                                     const float* __restrict__ w2,
                                                     const float* __restrict__ b2,
                                                     const float* __restrict__ lg,
                                                     const float* __restrict__ lb,
                                                     float* __restrict__ out) {
    extern __shared__ float sm[];
    float*  w1s = sm;                         // 16384 floats
    float*  w2s = sm + 16384;                 // 16384 floats
    float*  xs  = sm + 32768;                 // 8320 floats: [64 i][130 m] (reused as zs[128][65])
    __half* hs  = (__half*)(sm + 41088);      // 33280 halfs: [256 j][130 m]
    int tid = threadIdx.x;
    for (int i = tid; i < 4096; i += 512) {
        ((float4*)w1s)[i] = ((const float4*)w1)[i];
        ((float4*)w2s)[i] = ((const float4*)w2)[i];
    }
    int cg = tid & 63, mg = tid >> 6;      // phase1: 8 m-groups x 8 mp, 4 k-cols
    int cg2 = tid & 31, mg2 = tid >> 5;    // phase2: 16 m-groups x 4 mp, 2 k-cols
    int wid = tid >> 5, lane = tid & 31;
    u64 b1p[4], b2p[2];
#pragma unroll
    for (int k = 0; k < 4; k++) { float bv = b1[cg + 64 * k]; b1p[k] = pack2(bv, bv); }
#pragma unroll
    for (int k = 0; k < 2; k++) { float bv = b2[cg2 + 32 * k]; b2p[k] = pack2(bv, bv); }
    float lgA = lg[lane], lgB = lg[lane + 32], lbA = lb[lane], lbB = lb[lane + 32];
    __syncthreads();

    for (int tile = blockIdx.x; tile < FT; tile += 148) {
        int n0 = tile * 128;
        for (int idx = tid; idx < 8192; idx += 512) {
            int m = idx >> 6, i = idx & 63;
            xs[i * 130 + m] = g_x1[(n0 + m) * 64 + i];
        }
        __syncthreads();
        // ---- phase 1: h = relu(x1 @ W1 + b1) -> fp16 hs ----
        u64 acc[8][4];
#pragma unroll
        for (int mp = 0; mp < 8; mp++)
#pragma unroll
            for (int k = 0; k < 4; k++) acc[mp][k] = b1p[k];
#pragma unroll 4
        for (int i = 0; i < 64; i++) {
            u64 xp[8];
#pragma unroll
            for (int mp = 0; mp < 8; mp++) xp[mp] = *(const u64*)&xs[i * 130 + (mg * 8 + mp) * 2];
#pragma unroll
            for (int k = 0; k < 4; k++) {
                float wv = w1s[i * 256 + cg + 64 * k];
                u64 wp = pack2(wv, wv);
#pragma unroll
                for (int mp = 0; mp < 8; mp++) acc[mp][k] = fma2(xp[mp], wp, acc[mp][k]);
            }
        }
#pragma unroll
        for (int mp = 0; mp < 8; mp++)
#pragma unroll
            for (int k = 0; k < 4; k++) {
                float2 v = unpack2(acc[mp][k]);
                v.x = fmaxf(v.x, 0.f); v.y = fmaxf(v.y, 0.f);
                *(__half2*)&hs[(cg + 64 * k) * 130 + (mg * 8 + mp) * 2] = __floats2half2_rn(v.x, v.y);
            }
        __syncthreads();
        // ---- phase 2: y = h @ W2 + b2 ----
        u64 a2[4][2];
#pragma unroll
        for (int mp = 0; mp < 4; mp++)
#pragma unroll
            for (int k = 0; k < 2; k++) a2[mp][k] = b2p[k];
#pragma unroll 4
        for (int j = 0; j < 256; j++) {
            u64 hp[4];
#pragma unroll
            for (int mp = 0; mp < 4; mp++) {
                float2 hf = __half22float2(*(__half2*)&hs[j * 130 + (mg2 * 4 + mp) * 2]);
                hp[mp] = pack2(hf.x, hf.y);
            }
#pragma unroll
            for (int k = 0; k < 2; k++) {
                float wv = w2s[j * 64 + cg2 + 32 * k];
                u64 wp = pack2(wv, wv);
#pragma unroll
                for (int mp = 0; mp < 4; mp++) a2[mp][k] = fma2(hp[mp], wp, a2[mp][k]);
            }
        }
        // ---- residual (read xs to regs), then repack z into xs region as [m][c] ----
        float zr[4][2][2];
#pragma unroll
        for (int mp = 0; mp < 4; mp++)
#pragma unroll
            for (int k = 0; k < 2; k++) {
                int c = cg2 + 32 * k, m0 = (mg2 * 4 + mp) * 2;
                float2 v = unpack2(a2[mp][k]);
                zr[mp][k][0] = v.x + xs[c * 130 + m0];
                zr[mp][k][1] = v.y + xs[c * 130 + m0 + 1];
            }
        __syncthreads();
        float* zs = xs;                       // [128 m][65 c]
#pragma unroll
        for (int mp = 0; mp < 4; mp++)
#pragma unroll
            for (int k = 0; k < 2; k++) {
                int c = cg2 + 32 * k, m0 = (mg2 * 4 + mp) * 2;
                zs[m0 * 65 + c] = zr[mp][k][0];
                zs[(m0 + 1) * 65 + c] = zr[mp][k][1];
            }
        __syncthreads();
        // ---- LN2: 16 warps x 8 nodes ----
#pragma unroll
        for (int mm = 0; mm < 8; mm++) {
            int m = wid * 8 + mm;
            float z1 = zs[m * 65 + lane], z2 = zs[m * 65 + 32 + lane];
            float s = z1 + z2, q = z1 * z1 + z2 * z2;
#pragma unroll
            for (int o = 16; o; o >>= 1) {
                s += __shfl_xor_sync(0xffffffffu, s, o);
                q += __shfl_xor_sync(0xffffffffu, q, o);
            }
            float mean = s * (1.f / 64.f);
            float rstd = rsqrtf(q * (1.f / 64.f) - mean * mean + 1e-5f);
            int n = n0 + m;
            if (n < N_NODES) {
                out[n * 64 + lane]      = (z1 - mean) * rstd * lgA + lbA;
                out[n * 64 + lane + 32] = (z2 - mean) * rstd * lgB + lbB;
            }
        }
        __syncthreads();
    }
}

// ---------------- launch: CSR (1 memset + 3 kernels) forked under qkv ----------------
extern "C" void kernel_launch(void* const* d_in, const int* in_sizes, int n_in,
                              void* d_out, int out_size) {
    const float* x      = (const float*)d_in[0];
    const void*  ei     = d_in[1];
    const float* attn_w = (const float*)d_in[2];
    const float* attn_b = (const float*)d_in[3];
    const float* w1     = (const float*)d_in[4];
    const float* b1     = (const float*)d_in[5];
    const float* w2     = (const float*)d_in[6];
    const float* b2     = (const float*)d_in[7];
    const float* l1g    = (const float*)d_in[8];
    const float* l1b    = (const float*)d_in[9];
    const float* l2g    = (const float*)d_in[10];
    const float* l2b    = (const float*)d_in[11];
    float* out = (float*)d_out;

    static cudaStream_t s2 = nullptr;
    static cudaEvent_t evA = nullptr, evB = nullptr;
    static void* p_csr = nullptr;
    if (s2 == nullptr) {
        cudaStreamCreateWithFlags(&s2, cudaStreamNonBlocking);
        cudaEventCreateWithFlags(&evA, cudaEventDisableTiming);
        cudaEventCreateWithFlags(&evB, cudaEventDisableTiming);
        cudaGetSymbolAddress(&p_csr, g_csr);
    }

    cudaFuncSetAttribute(qkv_kernel, cudaFuncAttributeMaxDynamicSharedMemorySize, 66048);
    cudaFuncSetAttribute(ffn_kernel, cudaFuncAttributeMaxDynamicSharedMemorySize, 230912);

    // fork: CSR build chain on s2 (independent of qkv GEMM)
    cudaEventRecord(evA, 0);
    cudaStreamWaitEvent(s2, evA, 0);
    cudaMemsetAsync(p_csr, 0, sizeof(CsrScratch), s2);
    hist_detect_kernel<<<(N_EDGES + 255) / 256, 256, 0, s2>>>(ei);
    scan_kernel<<<NBLK, 256, 0, s2>>>();
    scatter_kernel<<<N_EDGES / 256, 256, 0, s2>>>(ei);
    cudaEventRecord(evB, s2);

    // main stream: qkv GEMM overlaps with CSR build
    qkv_kernel<<<(N_NODES + 63) / 64, 192, 66048>>>(x, attn_w, attn_b);

    // join, then attention + FFN
    cudaStreamWaitEvent(0, evB, 0);
    attn_kernel<<<(N_NODES + 7) / 8, 256>>>(x, l1g, l1b);
    ffn_kernel<<<148, 512, 230912>>>(w1, b1, w2, b2, l2g, l2b, out);
}

// round 15
// speedup vs baseline: 1.5609x; 1.5484x over previous
#include <cuda_runtime.h>
#include <cuda_fp16.h>

#define N_NODES 100000
#define N_EDGES 1600000
#define N_PAD   100032                       // qkv padding (64-node tiles)
#define N_PAD2  100096                       // ffn padding (128-node tiles, 782 tiles)
#define FT      782
#define NBLK    ((N_NODES + 255) / 256)      // 391 scan blocks
typedef unsigned long long u64;

// ---------------- device scratch (no allocations allowed) ----------------
__device__ float  g_q[N_PAD * 64];     // fp32 Q  [n][h*8+e]
__device__ __half g_kv[N_PAD * 128];   // fp16 KV [n][h*16 + (k:0-7 | v:8-15)] -> 32B/(node,head)
__device__ float  g_x1[N_PAD2 * 64];   // after attention + residual + LN1
__device__ int    g_ecol[N_EDGES];     // CSR column list
__device__ int    g_start[N_NODES];    // immutable CSR row starts (for attn)
__device__ int    g_startM[N_NODES];   // mutable; after scatter holds start+deg (row end)
__device__ int    g_is64;

// one contiguous zeroed-every-call region -> single cudaMemsetAsync
struct CsrScratch {
    int cnt[N_NODES];
    u64 pack[NBLK];   // lookback state (hi32: 1=partial 2=inclusive, lo32=value)
};
__device__ CsrScratch g_csr;

// ---------------- packed fp32x2 helpers (sm_100+) ----------------
__device__ __forceinline__ u64 fma2(u64 a, u64 b, u64 c) {
    u64 d; asm("fma.rn.f32x2 %0,%1,%2,%3;" : "=l"(d) : "l"(a), "l"(b), "l"(c)); return d;
}
__device__ __forceinline__ u64 pack2(float x, float y) {
    u64 d; asm("mov.b64 %0,{%1,%2};" : "=l"(d) : "f"(x), "f"(y)); return d;
}
__device__ __forceinline__ float2 unpack2(u64 v) {
    float2 r; asm("mov.b64 {%0,%1},%2;" : "=f"(r.x), "=f"(r.y) : "l"(v)); return r;
}

// ---------------- tensor-core helpers ----------------
__device__ __forceinline__ unsigned sptr(const void* p) {
    return (unsigned)__cvta_generic_to_shared(p);
}
#define LDSM4(r0,r1,r2,r3,addr) \
    asm volatile("ldmatrix.sync.aligned.m8n8.x4.shared.b16 {%0,%1,%2,%3}, [%4];" \
                 : "=r"(r0),"=r"(r1),"=r"(r2),"=r"(r3) : "r"(addr))
#define LDSM2T(r0,r1,addr) \
    asm volatile("ldmatrix.sync.aligned.m8n8.x2.trans.shared.b16 {%0,%1}, [%2];" \
                 : "=r"(r0),"=r"(r1) : "r"(addr))
#define MMA16816(c,a0,a1,a2,a3,b0,b1) \
    asm volatile("mma.sync.aligned.m16n8k16.row.col.f32.f16.f16.f32 " \
                 "{%0,%1,%2,%3}, {%4,%5,%6,%7}, {%8,%9}, {%0,%1,%2,%3};" \
                 : "+f"((c)[0]),"+f"((c)[1]),"+f"((c)[2]),"+f"((c)[3]) \
                 : "r"(a0),"r"(a1),"r"(a2),"r"(a3),"r"(b0),"r"(b1))

// ---------------- hist + per-block dtype detection ----------------
__global__ void hist_detect_kernel(const void* ei) {
    __shared__ int s_is64;
    int tid = threadIdx.x;
    if (tid < 32) {
        const long long* p = (const long long*)ei;
        long long v = p[tid];
        int ok = (v >= 0 && v < N_NODES);
        unsigned m = __ballot_sync(0xffffffffu, ok);
        if (tid == 0) {
            s_is64 = (m == 0xffffffffu);
            if (blockIdx.x == 0) g_is64 = s_is64;
        }
    }
    __syncthreads();
    int is64 = s_is64;
    int i = blockIdx.x * 256 + tid;
    if (i < N_EDGES) {
        int r = is64 ? (int)((const long long*)ei)[i] : ((const int*)ei)[i];
        atomicAdd(&g_csr.cnt[r], 1);
    }
}

// ---------------- single-pass decoupled-lookback exclusive scan ----------------
__global__ void scan_kernel() {
    __shared__ int s[256];
    __shared__ int s_off;
    int bid = blockIdx.x, tid = threadIdx.x;
    int i = bid * 256 + tid;
    int v = (i < N_NODES) ? g_csr.cnt[i] : 0;
    s[tid] = v;
    __syncthreads();
    for (int o = 1; o < 256; o <<= 1) {           // Hillis-Steele inclusive
        int t = (tid >= o) ? s[tid - o] : 0;
        __syncthreads();
        s[tid] += t;
        __syncthreads();
    }
    int total = s[255];
    if (tid == 0) {
        u64 st = (bid == 0) ? 2ULL : 1ULL;
        atomicExch(&g_csr.pack[bid], (st << 32) | (unsigned)total);
        s_off = 0;
    }
    __syncthreads();
    if (bid > 0 && tid < 32) {                    // warp-parallel lookback
        int off = 0, j = bid - 1;
        for (;;) {
            int idx = j - tid;
            u64 p = 0; int st = 0;
            if (idx >= 0) {
                do {
                    p = *(volatile u64*)&g_csr.pack[idx];
                    st = (int)(p >> 32);
                } while (st == 0);
            }
            unsigned inc_mask = __ballot_sync(0xffffffffu, idx >= 0 && st == 2);
            int val;
            if (inc_mask) {
                int lead = __ffs(inc_mask) - 1;
                val = (tid <= lead) ? (int)(unsigned)p : 0;
#pragma unroll
                for (int o = 16; o; o >>= 1) val += __shfl_xor_sync(0xffffffffu, val, o);
                off += val;
                break;
            } else {
                val = (idx >= 0) ? (int)(unsigned)p : 0;
#pragma unroll
                for (int o = 16; o; o >>= 1) val += __shfl_xor_sync(0xffffffffu, val, o);
                off += val;
                j -= 32;
                if (j < 0) break;
            }
        }
        if (tid == 0) {
            atomicExch(&g_csr.pack[bid], (2ULL << 32) | (unsigned)(off + total));
            s_off = off;
        }
    }
    __syncthreads();
    if (i < N_NODES) {
        int st = s_off + s[tid] - v;              // exclusive prefix
        g_start[i] = st;
        g_startM[i] = st;
    }
}

__global__ void scatter_kernel(const void* ei) {
    int i = blockIdx.x * 256 + threadIdx.x;       // 6250*256 == N_EDGES exactly
    int r, c;
    if (g_is64) {
        const long long* p = (const long long*)ei;
        r = (int)p[i]; c = (int)p[N_EDGES + i];
    } else {
        const int* p = (const int*)ei;
        r = p[i]; c = p[N_EDGES + i];
    }
    int pos = atomicAdd(&g_startM[r], 1);
    g_ecol[pos] = c;
}

// ---------------- qkv GEMM: x[100k,64] @ W[64,192] + b ----------------
__global__ __launch_bounds__(192, 3) void qkv_kernel(const float* __restrict__ x,
                                                     const float* __restrict__ w,
                                                     const float* __restrict__ bias) {
    extern __shared__ float sm[];
    float* ws = sm;            // 64*192
    float* xs = sm + 12288;    // [64 i][66 m-slots]
    int tid = threadIdx.x;
    for (int i = tid; i < 3072; i += 192) ((float4*)ws)[i] = ((const float4*)w)[i];
    int n0 = blockIdx.x * 64;
    for (int idx = tid; idx < 4096; idx += 192) {
        int m = idx >> 6, i = idx & 63;
        int r = n0 + m;
        xs[i * 66 + m] = (r < N_NODES) ? x[r * 64 + i] : 0.f;
    }
    __syncthreads();
    int cg = tid % 48, mg = tid / 48;
    u64 acc[8][4];
#pragma unroll
    for (int k = 0; k < 4; k++) {
        float bv = bias[cg + 48 * k];
        u64 bp = pack2(bv, bv);
#pragma unroll
        for (int mp = 0; mp < 8; mp++) acc[mp][k] = bp;
    }
#pragma unroll 4
    for (int i = 0; i < 64; i++) {
        u64 xp[8];
#pragma unroll
        for (int mp = 0; mp < 8; mp++) xp[mp] = *(const u64*)&xs[i * 66 + (mg * 8 + mp) * 2];
#pragma unroll
        for (int k = 0; k < 4; k++) {
            float wv = ws[i * 192 + cg + 48 * k];
            u64 wp = pack2(wv, wv);
#pragma unroll
            for (int mp = 0; mp < 8; mp++) acc[mp][k] = fma2(xp[mp], wp, acc[mp][k]);
        }
    }
#pragma unroll
    for (int mp = 0; mp < 8; mp++) {
        int m = n0 + (mg * 8 + mp) * 2;
#pragma unroll
        for (int k = 0; k < 4; k++) {
            int c = cg + 48 * k;
            int head = c / 24, r = c % 24;     // per-head interleave: q|k|v
            float2 v = unpack2(acc[mp][k]);
            if (r < 8) {
                int off = head * 8 + r;
                g_q[m * 64 + off] = v.x;
                g_q[(m + 1) * 64 + off] = v.y;
            } else {
                int off = head * 16 + (r - 8); // k: 0-7, v: 8-15 within head
                g_kv[m * 128 + off] = __float2half_rn(v.x);
                g_kv[(m + 1) * 128 + off] = __float2half_rn(v.y);
            }
        }
    }
}

// ---------------- fused attention gather + normalize + residual + LN1 ----------------
__global__ __launch_bounds__(256) void attn_kernel(const float* __restrict__ x,
                                                   const float* __restrict__ lg,
                                                   const float* __restrict__ lb) {
    __shared__ float sg[64], sb[64];
    int tid = threadIdx.x;
    if (tid < 64) sg[tid] = lg[tid];
    else if (tid < 128) sb[tid - 64] = lb[tid - 64];
    __syncthreads();
    int wid = tid >> 5, lane = tid & 31;
    int n = blockIdx.x * 8 + wid;
    int h = lane & 7, g = lane >> 3;
    const float4* qb = (const float4*)(g_q + n * 64 + h * 8);
    float4 q0 = qb[0], q1 = qb[1];
    __half2 qh0 = __floats2half2_rn(q0.x, q0.y);
    __half2 qh1 = __floats2half2_rn(q0.z, q0.w);
    __half2 qh2 = __floats2half2_rn(q1.x, q1.y);
    __half2 qh3 = __floats2half2_rn(q1.z, q1.w);
    const float4* xb = (const float4*)(x + n * 64 + h * 8);   // hoisted residual load
    float4 x0 = xb[0], x1v = xb[1];
    float den = 0.f;
    float a[8];
#pragma unroll
    for (int j = 0; j < 8; j++) a[j] = 0.f;
    int s = g_start[n];
    int e = g_startM[n];                           // = start[n] + deg[n] post-scatter
    int i = s + g;
    int c = (i < e) ? g_ecol[i] : 0;
    while (i < e) {
        int c_cur = c;
        i += 4;
        if (i < e) c = g_ecol[i];                  // prefetch next column index
        const uint4* p = (const uint4*)(g_kv + c_cur * 128 + h * 16);
        uint4 kr = p[0], vr = p[1];
        __half2 d2 = __hmul2(qh0, *(__half2*)&kr.x);
        d2 = __hfma2(qh1, *(__half2*)&kr.y, d2);
        d2 = __hfma2(qh2, *(__half2*)&kr.z, d2);
        d2 = __hfma2(qh3, *(__half2*)&kr.w, d2);
        float d = __low2float(d2) + __high2float(d2);
        float ev = __expf(d * 0.125f);
        den += ev;
        float2 v0 = __half22float2(*(__half2*)&vr.x);
        float2 v1 = __half22float2(*(__half2*)&vr.y);
        float2 v2 = __half22float2(*(__half2*)&vr.z);
        float2 v3 = __half22float2(*(__half2*)&vr.w);
        a[0] += ev * v0.x; a[1] += ev * v0.y; a[2] += ev * v1.x; a[3] += ev * v1.y;
        a[4] += ev * v2.x; a[5] += ev * v2.y; a[6] += ev * v3.x; a[7] += ev * v3.y;
    }
#pragma unroll
    for (int o = 8; o <= 16; o <<= 1) {
        den += __shfl_xor_sync(0xffffffffu, den, o);
#pragma unroll
        for (int j = 0; j < 8; j++) a[j] += __shfl_xor_sync(0xffffffffu, a[j], o);
    }
    float inv = (den > 0.f) ? 1.f / den : 0.f;
    float z[8];
    z[0] = x0.x + a[0] * inv;  z[1] = x0.y + a[1] * inv;
    z[2] = x0.z + a[2] * inv;  z[3] = x0.w + a[3] * inv;
    z[4] = x1v.x + a[4] * inv; z[5] = x1v.y + a[5] * inv;
    z[6] = x1v.z + a[6] * inv; z[7] = x1v.w + a[7] * inv;
    float sum = 0.f, sq = 0.f;
#pragma unroll
    for (int j = 0; j < 8; j++) { sum += z[j]; sq += z[j] * z[j]; }
#pragma unroll
    for (int o = 1; o < 8; o <<= 1) {
        sum += __shfl_xor_sync(0xffffffffu, sum, o);
        sq  += __shfl_xor_sync(0xffffffffu, sq, o);
    }
    float mean = sum * (1.f / 64.f);
    float rstd = rsqrtf(sq * (1.f / 64.f) - mean * mean + 1e-5f);
    if (g == 0) {
        float4 o0, o1;
        o0.x = (z[0] - mean) * rstd * sg[h * 8 + 0] + sb[h * 8 + 0];
        o0.y = (z[1] - mean) * rstd * sg[h * 8 + 1] + sb[h * 8 + 1];
        o0.z = (z[2] - mean) * rstd * sg[h * 8 + 2] + sb[h * 8 + 2];
        o0.w = (z[3] - mean) * rstd * sg[h * 8 + 3] + sb[h * 8 + 3];
        o1.x = (z[4] - mean) * rstd * sg[h * 8 + 4] + sb[h * 8 + 4];
        o1.y = (z[5] - mean) * rstd * sg[h * 8 + 5] + sb[h * 8 + 5];
        o1.z = (z[6] - mean) * rstd * sg[h * 8 + 6] + sb[h * 8 + 6];
        o1.w = (z[7] - mean) * rstd * sg[h * 8 + 7] + sb[h * 8 + 7];
        float4* ob = (float4*)(g_x1 + n * 64 + h * 8);
        ob[0] = o0; ob[1] = o1;
    }
}

// ---------------- FFN v3: tensor cores (mma.sync m16n8k16, fp16 in / fp32 acc) --------
// Persistent 148 CTAs x 512 threads, 128-node tiles.
// smem (bytes): w1s [64][264]h @0 (33792), w2s [256][72]h @33792 (36864),
//               xh [128][72]h @70656 (18432), hh [128][264]h @89088 (67584, reused as zs[128][66]f),
//               xs32 [128][66]f @156672 (33792), b1s [256]f @190464, b2s [64]f @191488. Total 191744.
// All smem row strides are 16B-odd multiples of 128B -> conflict-free ldmatrix.
#define SMEM_FFN 191744
__global__ __launch_bounds__(512, 1) void ffn_kernel(const float* __restrict__ w1,
                                                     const float* __restrict__ b1,
                                                     const float* __restrict__ w2,
                                                     const float* __restrict__ b2,
                                                     const float* __restrict__ lg,
                                                     const float* __restrict__ lb,
                                                     float* __restrict__ out) {
    extern __shared__ char smb[];
    __half* w1s = (__half*)(smb);              // [64][264]
    __half* w2s = (__half*)(smb + 33792);      // [256][72]
    __half* xh  = (__half*)(smb + 70656);      // [128][72]
    __half* hh  = (__half*)(smb + 89088);      // [128][264]
    float*  xs32= (float*)(smb + 156672);      // [128][66]
    float*  b1s = (float*)(smb + 190464);      // [256]
    float*  b2s = (float*)(smb + 191488);      // [64]
    float*  zs  = (float*)(smb + 89088);       // [128][66], reuses hh after phase 2

    int tid = threadIdx.x, lane = tid & 31, wid = tid >> 5;
    int mb = wid >> 1, nh = wid & 1;           // m-block 0-7, n-half 0-1
    // weights fp32 -> fp16 padded (once per CTA)
    for (int i = tid; i < 64 * 256; i += 512) {
        int r = i >> 8, c = i & 255;
        w1s[r * 264 + c] = __float2half_rn(w1[i]);
    }
    for (int i = tid; i < 256 * 64; i += 512) {
        int r = i >> 6, c = i & 63;
        w2s[r * 72 + c] = __float2half_rn(w2[i]);
    }
    if (tid < 256) b1s[tid] = b1[tid];
    if (tid < 64)  b2s[tid] = b2[tid];
    float lgA = lg[lane], lgB = lg[lane + 32], lbA = lb[lane], lbB = lb[lane + 32];
    __syncthreads();

    int lm16 = lane & 15;          // ldmatrix row-within-block
    int lhi8 = (lane >> 4) * 8;    // ldmatrix col offset (x4 A)
    int cgrp = (lane & 3) * 2;     // frag col pair base
    int rgrp = lane >> 2;          // frag row

    for (int tile = blockIdx.x; tile < FT; tile += 148) {
        int nb0 = tile * 128;
        for (int idx = tid; idx < 8192; idx += 512) {
            int m = idx >> 6, i = idx & 63;
            float v = g_x1[(nb0 + m) * 64 + i];
            xs32[m * 66 + i] = v;
            xh[m * 72 + i] = __float2half_rn(v);
        }
        __syncthreads();

        // ---- phase 1: H = relu(X @ W1 + b1), M128 N256 K64 ----
        float acc[16][4];
#pragma unroll
        for (int nb = 0; nb < 16; nb++) {
            int c0 = nh * 128 + nb * 8 + cgrp;
            acc[nb][0] = acc[nb][2] = b1s[c0];
            acc[nb][1] = acc[nb][3] = b1s[c0 + 1];
        }
#pragma unroll
        for (int ks = 0; ks < 4; ks++) {
            unsigned aad = sptr(&xh[(mb * 16 + lm16) * 72 + ks * 16 + lhi8]);
            unsigned a0, a1, a2, a3;
            LDSM4(a0, a1, a2, a3, aad);
#pragma unroll
            for (int nb = 0; nb < 16; nb++) {
                unsigned bad = sptr(&w1s[(ks * 16 + lm16) * 264 + nh * 128 + nb * 8]);
                unsigned bf0, bf1;
                LDSM2T(bf0, bf1, bad);
                MMA16816(acc[nb], a0, a1, a2, a3, bf0, bf1);
            }
        }
#pragma unroll
        for (int nb = 0; nb < 16; nb++) {
            int col = nh * 128 + nb * 8 + cgrp;
            int row = mb * 16 + rgrp;
            *(__half2*)&hh[row * 264 + col] =
                __floats2half2_rn(fmaxf(acc[nb][0], 0.f), fmaxf(acc[nb][1], 0.f));
            *(__half2*)&hh[(row + 8) * 264 + col] =
                __floats2half2_rn(fmaxf(acc[nb][2], 0.f), fmaxf(acc[nb][3], 0.f));
        }
        __syncthreads();

        // ---- phase 2: Y = H @ W2 + b2, M128 N64 K256 ----
        float c2[4][4];
#pragma unroll
        for (int nb = 0; nb < 4; nb++) {
            int c0 = nh * 32 + nb * 8 + cgrp;
            c2[nb][0] = c2[nb][2] = b2s[c0];
            c2[nb][1] = c2[nb][3] = b2s[c0 + 1];
        }
#pragma unroll 4
        for (int ks = 0; ks < 16; ks++) {
            unsigned aad = sptr(&hh[(mb * 16 + lm16) * 264 + ks * 16 + lhi8]);
            unsigned a0, a1, a2, a3;
            LDSM4(a0, a1, a2, a3, aad);
#pragma unroll
            for (int nb = 0; nb < 4; nb++) {
                unsigned bad = sptr(&w2s[(ks * 16 + lm16) * 72 + nh * 32 + nb * 8]);
                unsigned bf0, bf1;
                LDSM2T(bf0, bf1, bad);
                MMA16816(c2[nb], a0, a1, a2, a3, bf0, bf1);
            }
        }
        __syncthreads();   // all phase-2 hh reads done before zs overwrites it

        // ---- residual + stage z into zs (reuses hh region) ----
#pragma unroll
        for (int nb = 0; nb < 4; nb++) {
            int col = nh * 32 + nb * 8 + cgrp;
            int row = mb * 16 + rgrp;
            zs[row * 66 + col]           = c2[nb][0] + xs32[row * 66 + col];
            zs[row * 66 + col + 1]       = c2[nb][1] + xs32[row * 66 + col + 1];
            zs[(row + 8) * 66 + col]     = c2[nb][2] + xs32[(row + 8) * 66 + col];
            zs[(row + 8) * 66 + col + 1] = c2[nb][3] + xs32[(row + 8) * 66 + col + 1];
        }
        __syncthreads();

        // ---- LN2: 16 warps x 8 nodes ----
#pragma unroll
        for (int mm = 0; mm < 8; mm++) {
            int m = wid * 8 + mm;
            float z1 = zs[m * 66 + lane], z2 = zs[m * 66 + 32 + lane];
            float s = z1 + z2, q = z1 * z1 + z2 * z2;
#pragma unroll
            for (int o = 16; o; o >>= 1) {
                s += __shfl_xor_sync(0xffffffffu, s, o);
                q += __shfl_xor_sync(0xffffffffu, q, o);
            }
            float mean = s * (1.f / 64.f);
            float rstd = rsqrtf(q * (1.f / 64.f) - mean * mean + 1e-5f);
            int n = nb0 + m;
            if (n < N_NODES) {
                out[n * 64 + lane]      = (z1 - mean) * rstd * lgA + lbA;
                out[n * 64 + lane + 32] = (z2 - mean) * rstd * lgB + lbB;
            }
        }
        __syncthreads();
    }
}

// ---------------- launch: CSR (1 memset + 3 kernels) forked under qkv ----------------
extern "C" void kernel_launch(void* const* d_in, const int* in_sizes, int n_in,
                              void* d_out, int out_size) {
    const float* x      = (const float*)d_in[0];
    const void*  ei     = d_in[1];
    const float* attn_w = (const float*)d_in[2];
    const float* attn_b = (const float*)d_in[3];
    const float* w1     = (const float*)d_in[4];
    const float* b1     = (const float*)d_in[5];
    const float* w2     = (const float*)d_in[6];
    const float* b2     = (const float*)d_in[7];
    const float* l1g    = (const float*)d_in[8];
    const float* l1b    = (const float*)d_in[9];
    const float* l2g    = (const float*)d_in[10];
    const float* l2b    = (const float*)d_in[11];
    float* out = (float*)d_out;

    static cudaStream_t s2 = nullptr;
    static cudaEvent_t evA = nullptr, evB = nullptr;
    static void* p_csr = nullptr;
    if (s2 == nullptr) {
        cudaStreamCreateWithFlags(&s2, cudaStreamNonBlocking);
        cudaEventCreateWithFlags(&evA, cudaEventDisableTiming);
        cudaEventCreateWithFlags(&evB, cudaEventDisableTiming);
        cudaGetSymbolAddress(&p_csr, g_csr);
    }

    cudaFuncSetAttribute(qkv_kernel, cudaFuncAttributeMaxDynamicSharedMemorySize, 66048);
    cudaFuncSetAttribute(ffn_kernel, cudaFuncAttributeMaxDynamicSharedMemorySize, SMEM_FFN);

    // fork: CSR build chain on s2 (independent of qkv GEMM)
    cudaEventRecord(evA, 0);
    cudaStreamWaitEvent(s2, evA, 0);
    cudaMemsetAsync(p_csr, 0, sizeof(CsrScratch), s2);
    hist_detect_kernel<<<(N_EDGES + 255) / 256, 256, 0, s2>>>(ei);
    scan_kernel<<<NBLK, 256, 0, s2>>>();
    scatter_kernel<<<N_EDGES / 256, 256, 0, s2>>>(ei);
    cudaEventRecord(evB, s2);

    // main stream: qkv GEMM overlaps with CSR build
    qkv_kernel<<<(N_NODES + 63) / 64, 192, 66048>>>(x, attn_w, attn_b);

    // join, then attention + FFN
    cudaStreamWaitEvent(0, evB, 0);
    attn_kernel<<<(N_NODES + 7) / 8, 256>>>(x, l1g, l1b);
    ffn_kernel<<<148, 512, SMEM_FFN>>>(w1, b1, w2, b2, l2g, l2b, out);
}